// round 16
// baseline (speedup 1.0000x reference)
#include <cuda_runtime.h>
#include <cuda_bf16.h>
#include <cstdint>

#define BB 2
#define HH 128
#define WW 128
#define CC 128
#define NBR 9
#define TILE_P 16
#define NEDGE 144
#define NT 512

#define KP 152                 /* padded edge-A cols */
#define ROWB (KP*2)            /* 304 B rows (conflict-free ldmatrix) */
#define CROWB 272              /* cen/ws tile row stride bytes */

// ---- smem float indices (misc block = 3008 floats = 12032 B) ----
#define F_PART  0       /* [144][16] per-(edge, n16) partials */
#define F_GATE  2304
#define F_SG    2448
#define F_INVM  2464
#define F_W2    2496    /* [256]: dW2 | rW2 */
#define F_VBO   2752    /* [128] vb@oW */
#define F_OB    2880    /* [128] ob */
// ---- smem byte offsets (main kernel) ----
#define CU_OFFB   12032
#define CW_OFFB   (CU_OFFB + 16384)           // 28416
#define A_OFFB    (CW_OFFB + 4352)            // 32768
#define SMEM_TOTAL (A_OFFB + 43776)           // 76544
#define SETUP_SMEM 38912                      // 128 rows x 304 staging (half-buffer)

// ---- device scratch ----
__device__ float g_norm[BB*HH*WW*CC];
__device__ float g_vbo[CC];
__device__ uint32_t g_map[1152];
__device__ uint4 g_Bfrag[16*9*32];           // edge B fragments [n16][k][lane]
__device__ uint4 g_Ufrag[16*8*32];           // U fragments
__device__ uint4 g_Wfrag[8*8*32];            // Wcomb fragments

// ---- helpers ----
__device__ __forceinline__ float gelu_exact(float x) {
    return 0.5f * x * (1.0f + erff(x * 0.70710678118654752f));
}
__device__ __forceinline__ uint32_t smem_u32(const void* p) {
    uint32_t a;
    asm("{ .reg .u64 t; cvta.to.shared.u64 t, %1; cvt.u32.u64 %0, t; }" : "=r"(a) : "l"(p));
    return a;
}
__device__ __forceinline__ void ldm_x4(uint32_t* r, uint32_t addr) {
    asm volatile("ldmatrix.sync.aligned.m8n8.x4.shared.b16 {%0,%1,%2,%3}, [%4];"
        : "=r"(r[0]), "=r"(r[1]), "=r"(r[2]), "=r"(r[3]) : "r"(addr));
}
__device__ __forceinline__ void mma16816(float* c, const uint32_t* a, uint32_t b0, uint32_t b1) {
    asm volatile("mma.sync.aligned.m16n8k16.row.col.f32.bf16.bf16.f32 "
        "{%0,%1,%2,%3}, {%4,%5,%6,%7}, {%8,%9}, {%0,%1,%2,%3};"
        : "+f"(c[0]), "+f"(c[1]), "+f"(c[2]), "+f"(c[3])
        : "r"(a[0]), "r"(a[1]), "r"(a[2]), "r"(a[3]), "r"(b0), "r"(b1));
}

__device__ __forceinline__ float b_val(int j, int c,
        const float* dW1, const float* db1, const float* rW1, const float* rb1,
        const float* rel_pos) {
    float val = 0.0f;
    if (c < 128) {
        val = (j < 128) ? dW1[(128 + c)*CC + j]       - dW1[(256 + c)*CC + j]
                        : rW1[(128 + c)*CC + (j-128)] - rW1[(256 + c)*CC + (j-128)];
    } else if (c < 137) {
        int n = c - 128;
        if (j < 128) {
            float bd = db1[j];
            #pragma unroll
            for (int r = 0; r < 8; ++r) bd += rel_pos[n*8 + r] * dW1[(384 + r)*CC + j];
            val = bd;
        } else {
            float br = rb1[j - 128];
            #pragma unroll
            for (int r = 0; r < 8; ++r) br += rel_pos[n*8 + r] * rW1[(384 + r)*CC + (j-128)];
            val = br;
        }
    }
    return val;
}

// ================= setup: LN1 (0..2047) + frag builders (2048..2051) =================
__global__ void setup_kernel(const float* __restrict__ tokens,
                             const float* __restrict__ g, const float* __restrict__ b,
                             const float* __restrict__ dW1, const float* __restrict__ db1,
                             const float* __restrict__ rW1, const float* __restrict__ rb1,
                             const float* __restrict__ rel_pos,
                             const float* __restrict__ vW, const float* __restrict__ oW,
                             const float* __restrict__ vb) {
    extern __shared__ char s[];
    const int tid = threadIdx.x;
    const int warp = tid >> 5, lane = tid & 31;
    const uint32_t sb = smem_u32(s);

    if (blockIdx.x < 2048) {
        // --- LN1: 16 rows per block ---
        int row = blockIdx.x * 16 + warp;
        float4 x = reinterpret_cast<const float4*>(tokens + (long)row*CC)[lane];
        float su = x.x + x.y + x.z + x.w;
        #pragma unroll
        for (int o = 16; o; o >>= 1) su += __shfl_xor_sync(0xffffffffu, su, o);
        float m = su * (1.0f/128.0f);
        float dx = x.x - m, dy = x.y - m, dz = x.z - m, dw = x.w - m;
        float v = dx*dx + dy*dy + dz*dz + dw*dw;
        #pragma unroll
        for (int o = 16; o; o >>= 1) v += __shfl_xor_sync(0xffffffffu, v, o);
        float rs = rsqrtf(v * (1.0f/128.0f) + 1e-5f);
        int c = lane * 4;
        float4 o4;
        o4.x = dx*rs*g[c+0] + b[c+0];
        o4.y = dy*rs*g[c+1] + b[c+1];
        o4.z = dz*rs*g[c+2] + b[c+2];
        o4.w = dw*rs*g[c+3] + b[c+3];
        reinterpret_cast<float4*>(g_norm + (long)row*CC)[lane] = o4;
    } else if (blockIdx.x == 2048) {
        // --- edge B fragments (V fold + bias one-hot cols), 2 halves of 128 rows ---
        #pragma unroll 1
        for (int half = 0; half < 2; ++half) {
            for (int idx = tid; idx < 128*KP; idx += NT) {
                int j = idx / KP, c = idx - (idx / KP)*KP;
                *(__nv_bfloat16*)(s + j*ROWB + c*2) =
                    __float2bfloat16(b_val(half*128 + j, c, dW1, db1, rW1, rb1, rel_pos));
            }
            __syncthreads();
            if (warp < 8) {
                int ni = half*8 + warp;
                uint32_t baddr = sb + (uint32_t)((warp*16 + (lane & 7) + ((lane >> 4) << 3))*ROWB
                               + (((lane >> 3) & 1) << 4));
                #pragma unroll
                for (int k = 0; k < 9; ++k) {
                    uint32_t bf[4];
                    ldm_x4(bf, baddr + k*32);
                    g_Bfrag[(ni*9 + k)*32 + lane] = make_uint4(bf[0], bf[1], bf[2], bf[3]);
                }
            }
            __syncthreads();
        }
    } else if (blockIdx.x == 2049) {
        // --- U fragments, 2 halves ---
        #pragma unroll 1
        for (int half = 0; half < 2; ++half) {
            for (int idx = tid; idx < 128*128; idx += NT) {
                int j = idx >> 7, c = idx & 127;
                int jg = half*128 + j;
                float val = (jg < 128)
                    ? dW1[c*CC + jg]         + dW1[(256 + c)*CC + jg]
                    : rW1[c*CC + (jg - 128)] + rW1[(256 + c)*CC + (jg - 128)];
                *(__nv_bfloat16*)(s + j*CROWB + c*2) = __float2bfloat16(val);
            }
            __syncthreads();
            if (warp < 8) {
                int ni = half*8 + warp;
                uint32_t baddr = sb + (uint32_t)((warp*16 + (lane & 7) + ((lane >> 4) << 3))*CROWB
                               + (((lane >> 3) & 1) << 4));
                #pragma unroll
                for (int k = 0; k < 8; ++k) {
                    uint32_t bf[4];
                    ldm_x4(bf, baddr + k*32);
                    g_Ufrag[(ni*8 + k)*32 + lane] = make_uint4(bf[0], bf[1], bf[2], bf[3]);
                }
            }
            __syncthreads();
        }
    } else if (blockIdx.x == 2050) {
        // --- Wcomb fragments + vbo ---
        for (int idx = tid; idx < 128*128; idx += NT) {
            int c = idx >> 7, j = idx & 127;
            float su = 0.0f;
            #pragma unroll 4
            for (int e = 0; e < 128; ++e) su = fmaf(vW[c*CC + e], oW[e*CC + j], su);
            *(__nv_bfloat16*)(s + j*CROWB + c*2) = __float2bfloat16(su);
        }
        if (tid < 128) {
            float su = 0.0f;
            #pragma unroll 4
            for (int e = 0; e < 128; ++e) su = fmaf(vb[e], oW[e*CC + tid], su);
            g_vbo[tid] = su;
        }
        __syncthreads();
        if (warp < 8) {
            uint32_t baddr = sb + (uint32_t)((warp*16 + (lane & 7) + ((lane >> 4) << 3))*CROWB
                           + (((lane >> 3) & 1) << 4));
            #pragma unroll
            for (int k = 0; k < 8; ++k) {
                uint32_t bf[4];
                ldm_x4(bf, baddr + k*32);
                g_Wfrag[(warp*8 + k)*32 + lane] = make_uint4(bf[0], bf[1], bf[2], bf[3]);
            }
        }
    } else {
        // --- gather map ---
        for (int r0 = tid; r0 < 1152; r0 += NT) {
            int sft = r0 >> 7;
            int c2  = r0 & 127;
            int f   = c2*9 + sft;
            int n   = f >> 7;
            int c   = f & 127;
            int di  = sft / 3;
            int dj  = sft - di*3;
            uint32_t dst = (uint32_t)(n*ROWB + c*2);
            g_map[r0] = (dst << 11) | ((uint32_t)di << 9) | ((uint32_t)dj << 7) | (uint32_t)c2;
        }
    }
}

// ================= main fused kernel: CTA = 16 positions (R13 config) =================
__global__ __launch_bounds__(NT, 2)
void eml_main_kernel(const float* __restrict__ tokens,
                     const float* __restrict__ ln2_g, const float* __restrict__ ln2_b,
                     const float* __restrict__ dW2, const float* __restrict__ db2,
                     const float* __restrict__ rW2, const float* __restrict__ rb2,
                     const float* __restrict__ ob,
                     const float* __restrict__ p_gamma, const float* __restrict__ p_lam,
                     const float* __restrict__ p_bias,
                     float* __restrict__ out) {
    extern __shared__ char smem[];
    float* smf = (float*)smem;
    float* cuS = (float*)(smem + CU_OFFB);        // [16][256]
    float* uS  = (float*)(smem + A_OFFB);         // aliases edge A (dead by then)
    const uint32_t smb = smem_u32(smem);

    const int tid  = threadIdx.x;
    const int warp = tid >> 5, lane = tid & 31;
    const int blk = blockIdx.x;
    const int b   = blk >> 10;
    const int t   = blk & 1023;
    const int h   = t >> 3;
    const int w0  = (t & 7) << 4;
    const int rowbase = (b*HH + h)*WW + w0;

    // ---- phase 0: ext-col zero + one-hot; cen bf16 stage; w2/vbo/ob ----
    if (tid < NEDGE) {
        char* row = smem + A_OFFB + tid*ROWB;
        uint4 z = make_uint4(0, 0, 0, 0);
        *(uint4*)(row + 256) = z;
        *(uint4*)(row + 272) = z;
        *(uint4*)(row + 288) = z;
        int n = tid - (tid / 9)*9;
        *(__nv_bfloat16*)(row + (128 + n)*2) = __float2bfloat16(1.0f);
    }
    for (int i = tid; i < 1024; i += NT) {
        int p = i >> 6, cp = i & 63;
        float2 v = *(const float2*)(g_norm + (long)(rowbase + p)*CC + cp*2);
        *(__nv_bfloat162*)(smem + CW_OFFB + p*CROWB + cp*4) = __floats2bfloat162_rn(v.x, v.y);
    }
    if (tid < 256)      smf[F_W2 + tid] = (tid < 128) ? dW2[tid] : rW2[tid - 128];
    else if (tid < 384) smf[F_VBO + tid - 256] = g_vbo[tid - 256];
    else                smf[F_OB + tid - 384]  = ob[tid - 384];

    // ---- phase 1: map-based gather -> edge A bf16 ----
    for (int r0 = tid; r0 < 1152; r0 += NT) {
        uint32_t pk = g_map[r0];
        int c2 = pk & 127;
        int dj = (pk >> 7) & 3;
        int di = (pk >> 9) & 3;
        uint32_t dst = pk >> 11;
        int hh = h + di - 1;
        bool hok = (unsigned)hh < HH;
        long srow = (long)(b*HH + hh)*WW;
        char* dbase = smem + A_OFFB + dst;
        #pragma unroll
        for (int p = 0; p < 16; ++p) {
            int ww = w0 + p + dj - 1;
            float val = 0.0f;
            if (hok && (unsigned)ww < WW) val = g_norm[(srow + ww)*CC + c2];
            *(__nv_bfloat16*)(dbase + p*(9*ROWB)) = __float2bfloat16(val);
        }
    }
    __syncthreads();

    // ---- phase 2: cu GEMM (cen @ U) ----
    {
        uint32_t aaddr = smb + CW_OFFB + (lane & 15)*CROWB + ((lane >> 4) << 4);
        uint32_t af[8][4];
        #pragma unroll
        for (int k = 0; k < 8; ++k) ldm_x4(af[k], aaddr + k*32);
        float cA[4] = {0,0,0,0}, cB[4] = {0,0,0,0};
        const uint4* up = g_Ufrag + (warp*8)*32 + lane;
        #pragma unroll
        for (int k = 0; k < 8; ++k) {
            uint4 bf = up[k*32];
            mma16816(cA, af[k], bf.x, bf.y);
            mma16816(cB, af[k], bf.z, bf.w);
        }
        int r = lane >> 2, jc = warp*16 + (lane & 3)*2;
        cuS[r*256 + jc]           = cA[0];
        cuS[r*256 + jc + 1]       = cA[1];
        cuS[(r + 8)*256 + jc]     = cA[2];
        cuS[(r + 8)*256 + jc + 1] = cA[3];
        cuS[r*256 + jc + 8]       = cB[0];
        cuS[r*256 + jc + 9]       = cB[1];
        cuS[(r + 8)*256 + jc + 8] = cB[2];
        cuS[(r + 8)*256 + jc + 9] = cB[3];
    }
    __syncthreads();

    // ---- phase 3: edge GEMM, warp = n16 block (9 m-tiles each) ----
    {
        const uint32_t Abase = smb + A_OFFB;
        const int ni = warp;
        const uint4* bp = g_Bfrag + (ni*9)*32 + lane;
        const int jgg = ni*16 + (lane & 3)*2;
        const float w20 = smf[F_W2 + jgg],     w21 = smf[F_W2 + jgg + 1];
        const float w28 = smf[F_W2 + jgg + 8], w29 = smf[F_W2 + jgg + 9];
        #pragma unroll
        for (int mt = 0; mt < 9; ++mt) {
            int m0 = mt * 16;
            int r0 = m0 + (lane >> 2);
            int p0 = r0 / 9, p1 = (r0 + 8) / 9;
            uint32_t aaddr = Abase + (m0 + (lane & 15))*ROWB + ((lane >> 4) << 4);
            float acc[8];
            #pragma unroll
            for (int q = 0; q < 8; ++q) acc[q] = 0.0f;
            #pragma unroll
            for (int k = 0; k < 9; ++k) {
                uint32_t af[4];
                ldm_x4(af, aaddr + k*32);
                uint4 bf = bp[k*32];
                mma16816(acc,     af, bf.x, bf.y);
                mma16816(acc + 4, af, bf.z, bf.w);
            }
            const float* cu0 = cuS + p0*256 + jgg;
            const float* cu1 = cuS + p1*256 + jgg;
            float part0 = gelu_exact(acc[0] + cu0[0])*w20 + gelu_exact(acc[1] + cu0[1])*w21
                        + gelu_exact(acc[4] + cu0[8])*w28 + gelu_exact(acc[5] + cu0[9])*w29;
            float part1 = gelu_exact(acc[2] + cu1[0])*w20 + gelu_exact(acc[3] + cu1[1])*w21
                        + gelu_exact(acc[6] + cu1[8])*w28 + gelu_exact(acc[7] + cu1[9])*w29;
            part0 += __shfl_xor_sync(0xffffffffu, part0, 1);
            part0 += __shfl_xor_sync(0xffffffffu, part0, 2);
            part1 += __shfl_xor_sync(0xffffffffu, part1, 1);
            part1 += __shfl_xor_sync(0xffffffffu, part1, 2);
            if ((lane & 3) == 0) {
                smf[F_PART + r0*16 + ni]       = part0;
                smf[F_PART + (r0 + 8)*16 + ni] = part1;
            }
        }
    }
    __syncthreads();

    // ---- phase 4: EML gate ----
    const float gamma = *p_gamma, lam = *p_lam, ebias = *p_bias;
    if (tid < NEDGE) {
        const float4* pr = (const float4*)(smf + F_PART + tid*16);
        float4 a = pr[0], b4 = pr[1], c4 = pr[2], e4 = pr[3];
        float d = a.x + a.y + a.z + a.w + b4.x + b4.y + b4.z + b4.w + db2[0];
        float r = c4.x + c4.y + c4.z + c4.w + e4.x + e4.y + e4.z + e4.w + rb2[0];
        float sp = fmaxf(r, 0.0f) + log1pf(expf(-fabsf(r)));
        float en = gamma * d / (lam * sp + 1e-6f) + ebias;
        en = fminf(fmaxf(en, -3.0f), 3.0f);
        smf[F_GATE + tid] = 1.0f / (1.0f + expf(-en));
    }
    __syncthreads();
    if (tid < TILE_P) {
        float s = 0.0f;
        #pragma unroll
        for (int n = 0; n < 9; ++n) s += smf[F_GATE + tid*9 + n];
        smf[F_SG + tid]   = s;
        smf[F_INVM + tid] = 1.0f / fmaxf(s, 1e-6f);
    }
    __syncthreads();

    // ---- phase 5: ws = (sum_n gate*nbhd)/mass -> bf16 tile ----
    {
        int p = tid >> 5;
        int c0 = lane * 4;
        float im = smf[F_INVM + p];
        float gr[9];
        #pragma unroll
        for (int n = 0; n < 9; ++n) gr[n] = smf[F_GATE + p*9 + n];
        float s0 = 0, s1 = 0, s2 = 0, s3 = 0;
        #pragma unroll
        for (int n = 0; n < 9; ++n) {
            const char* row = smem + A_OFFB + (p*9 + n)*ROWB;
            uint2 u = *(const uint2*)(row + c0*2);
            __nv_bfloat162 lo = *reinterpret_cast<__nv_bfloat162*>(&u.x);
            __nv_bfloat162 hi = *reinterpret_cast<__nv_bfloat162*>(&u.y);
            s0 += gr[n] * __bfloat162float(lo.x);
            s1 += gr[n] * __bfloat162float(lo.y);
            s2 += gr[n] * __bfloat162float(hi.x);
            s3 += gr[n] * __bfloat162float(hi.y);
        }
        __nv_bfloat162 lo2 = __floats2bfloat162_rn(s0*im, s1*im);
        __nv_bfloat162 hi2 = __floats2bfloat162_rn(s2*im, s3*im);
        uint2 st;
        st.x = *reinterpret_cast<uint32_t*>(&lo2);
        st.y = *reinterpret_cast<uint32_t*>(&hi2);
        *(uint2*)(smem + CW_OFFB + p*CROWB + c0*2) = st;
    }
    __syncthreads();

    // ---- phase 6: u GEMM (ws @ Wcomb) + tokens + coef*vbo + ob -> uS f32 ----
    if (warp < 8) {
        uint32_t aaddr = smb + CW_OFFB + (lane & 15)*CROWB + ((lane >> 4) << 4);
        uint32_t af[8][4];
        #pragma unroll
        for (int k = 0; k < 8; ++k) ldm_x4(af[k], aaddr + k*32);
        float cA[4] = {0,0,0,0}, cB[4] = {0,0,0,0};
        const uint4* wp = g_Wfrag + (warp*8)*32 + lane;
        #pragma unroll
        for (int k = 0; k < 8; ++k) {
            uint4 bf = wp[k*32];
            mma16816(cA, af[k], bf.x, bf.y);
            mma16816(cB, af[k], bf.z, bf.w);
        }
        int r = lane >> 2, jc = (lane & 3)*2, j0 = warp*16;
        int p0 = r, p1 = r + 8;
        float coef0 = smf[F_SG + p0] * smf[F_INVM + p0];
        float coef1 = smf[F_SG + p1] * smf[F_INVM + p1];
        int d00 = j0 + jc, d10 = j0 + 8 + jc;
        float2 tA0 = *(const float2*)(tokens + (long)(rowbase + p0)*CC + d00);
        float2 tA1 = *(const float2*)(tokens + (long)(rowbase + p0)*CC + d10);
        float2 tB0 = *(const float2*)(tokens + (long)(rowbase + p1)*CC + d00);
        float2 tB1 = *(const float2*)(tokens + (long)(rowbase + p1)*CC + d10);
        uS[p0*CC + d00]     = cA[0] + tA0.x + coef0*smf[F_VBO + d00]     + smf[F_OB + d00];
        uS[p0*CC + d00 + 1] = cA[1] + tA0.y + coef0*smf[F_VBO + d00 + 1] + smf[F_OB + d00 + 1];
        uS[p1*CC + d00]     = cA[2] + tB0.x + coef1*smf[F_VBO + d00]     + smf[F_OB + d00];
        uS[p1*CC + d00 + 1] = cA[3] + tB0.y + coef1*smf[F_VBO + d00 + 1] + smf[F_OB + d00 + 1];
        uS[p0*CC + d10]     = cB[0] + tA1.x + coef0*smf[F_VBO + d10]     + smf[F_OB + d10];
        uS[p0*CC + d10 + 1] = cB[1] + tA1.y + coef0*smf[F_VBO + d10 + 1] + smf[F_OB + d10 + 1];
        uS[p1*CC + d10]     = cB[2] + tB1.x + coef1*smf[F_VBO + d10]     + smf[F_OB + d10];
        uS[p1*CC + d10 + 1] = cB[3] + tB1.y + coef1*smf[F_VBO + d10 + 1] + smf[F_OB + d10 + 1];
    }
    __syncthreads();

    // ---- phase 7: LN2 + store (warp per position) ----
    {
        int p = warp;
        float4 x = reinterpret_cast<const float4*>(uS + p*CC)[lane];
        float s = x.x + x.y + x.z + x.w;
        #pragma unroll
        for (int o = 16; o; o >>= 1) s += __shfl_xor_sync(0xffffffffu, s, o);
        float m = s * (1.0f/128.0f);
        float dx = x.x - m, dy = x.y - m, dz = x.z - m, dw = x.w - m;
        float v = dx*dx + dy*dy + dz*dz + dw*dw;
        #pragma unroll
        for (int o = 16; o; o >>= 1) v += __shfl_xor_sync(0xffffffffu, v, o);
        float rs = rsqrtf(v * (1.0f/128.0f) + 1e-5f);
        int c = lane * 4;
        float4 o4;
        o4.x = dx*rs*ln2_g[c+0] + ln2_b[c+0];
        o4.y = dy*rs*ln2_g[c+1] + ln2_b[c+1];
        o4.z = dz*rs*ln2_g[c+2] + ln2_b[c+2];
        o4.w = dw*rs*ln2_g[c+3] + ln2_b[c+3];
        reinterpret_cast<float4*>(out + (long)(rowbase + p)*CC)[lane] = o4;
    }
}

// ---------------- launch ----------------
extern "C" void kernel_launch(void* const* d_in, const int* in_sizes, int n_in,
                              void* d_out, int out_size) {
    const float* tokens = (const float*)d_in[0];
    const float* ln1_g  = (const float*)d_in[1];
    const float* ln1_b  = (const float*)d_in[2];
    const float* ln2_g  = (const float*)d_in[3];
    const float* ln2_b  = (const float*)d_in[4];
    const float* rel_pos= (const float*)d_in[5];
    const float* dW1    = (const float*)d_in[6];
    const float* db1    = (const float*)d_in[7];
    const float* dW2    = (const float*)d_in[8];
    const float* db2    = (const float*)d_in[9];
    const float* rW1    = (const float*)d_in[10];
    const float* rb1    = (const float*)d_in[11];
    const float* rW2    = (const float*)d_in[12];
    const float* rb2    = (const float*)d_in[13];
    const float* vW     = (const float*)d_in[14];
    const float* vb     = (const float*)d_in[15];
    const float* oW     = (const float*)d_in[16];
    const float* ob     = (const float*)d_in[17];
    const float* gamma  = (const float*)d_in[18];
    const float* lam    = (const float*)d_in[19];
    const float* ebias  = (const float*)d_in[20];
    float* out = (float*)d_out;

    cudaFuncSetAttribute(setup_kernel, cudaFuncAttributeMaxDynamicSharedMemorySize, SETUP_SMEM);
    setup_kernel<<<2052, NT, SETUP_SMEM>>>(tokens, ln1_g, ln1_b, dW1, db1, rW1, rb1,
                                           rel_pos, vW, oW, vb);
    cudaFuncSetAttribute(eml_main_kernel, cudaFuncAttributeMaxDynamicSharedMemorySize, SMEM_TOTAL);
    eml_main_kernel<<<(BB*HH*WW)/TILE_P, NT, SMEM_TOTAL>>>(tokens, ln2_g, ln2_b, dW2, db2,
                                                           rW2, rb2, ob,
                                                           gamma, lam, ebias, out);
}

// round 17
// speedup vs baseline: 1.3986x; 1.3986x over previous
#include <cuda_runtime.h>
#include <cuda_bf16.h>
#include <cstdint>

#define BB 2
#define HH 128
#define WW 128
#define CC 128
#define NBR 9
#define TILE_P 16
#define NEDGE 144
#define NT 512

#define KP 152                 /* padded edge-A cols */
#define ROWB (KP*2)            /* 304 B rows (conflict-free ldmatrix) */
#define CROWB 272              /* halo/ws row stride bytes (136 bf16 cols) */

// ---- smem float indices (misc block = 3008 floats = 12032 B) ----
#define F_PART  0       /* [144][16] */
#define F_GATE  2304
#define F_SG    2448
#define F_INVM  2464
#define F_W2    2496    /* [256]: dW2 | rW2 */
#define F_VBO   2752
#define F_OB    2880
// ---- smem byte offsets (main kernel) ----
#define CU_OFFB   12032                       // [16][256] f32 (16384)
#define HALO_OFFB (CU_OFFB + 16384)           // 28416: [54][CROWB] bf16 LN halo (14688)
#define WS_OFFB   (HALO_OFFB + 19*CROWB)      // 33584: ws/cen tile = halo rows 19..34
#define A_OFFB    (HALO_OFFB + 54*CROWB)      // 43104: edge A 144 x 304 (43776)
#define SMEM_TOTAL (A_OFFB + 43776)           // 86880
#define SETUP_SMEM 12544                      // oW stage (8192) + frag stage (4352)

// ---- device scratch ----
__device__ float g_vbo[CC];
__device__ uint32_t g_map[1152];
__device__ uint4 g_Bfrag[16*9*32];           // edge B fragments [n16][k][lane]
__device__ uint4 g_Ufrag[16*8*32];           // U fragments
__device__ uint4 g_Wfrag[8*8*32];            // Wcomb fragments

// ---- helpers ----
__device__ __forceinline__ float gelu_exact(float x) {
    return 0.5f * x * (1.0f + erff(x * 0.70710678118654752f));
}
__device__ __forceinline__ uint32_t smem_u32(const void* p) {
    uint32_t a;
    asm("{ .reg .u64 t; cvta.to.shared.u64 t, %1; cvt.u32.u64 %0, t; }" : "=r"(a) : "l"(p));
    return a;
}
__device__ __forceinline__ void ldm_x4(uint32_t* r, uint32_t addr) {
    asm volatile("ldmatrix.sync.aligned.m8n8.x4.shared.b16 {%0,%1,%2,%3}, [%4];"
        : "=r"(r[0]), "=r"(r[1]), "=r"(r[2]), "=r"(r[3]) : "r"(addr));
}
__device__ __forceinline__ void mma16816(float* c, const uint32_t* a, uint32_t b0, uint32_t b1) {
    asm volatile("mma.sync.aligned.m16n8k16.row.col.f32.bf16.bf16.f32 "
        "{%0,%1,%2,%3}, {%4,%5,%6,%7}, {%8,%9}, {%0,%1,%2,%3};"
        : "+f"(c[0]), "+f"(c[1]), "+f"(c[2]), "+f"(c[3])
        : "r"(a[0]), "r"(a[1]), "r"(a[2]), "r"(a[3]), "r"(b0), "r"(b1));
}

__device__ __forceinline__ float b_val(int j, int c,
        const float* dW1, const float* db1, const float* rW1, const float* rb1,
        const float* rel_pos) {
    float val = 0.0f;
    if (c < 128) {
        val = (j < 128) ? dW1[(128 + c)*CC + j]       - dW1[(256 + c)*CC + j]
                        : rW1[(128 + c)*CC + (j-128)] - rW1[(256 + c)*CC + (j-128)];
    } else if (c < 137) {
        int n = c - 128;
        if (j < 128) {
            float bd = db1[j];
            #pragma unroll
            for (int r = 0; r < 8; ++r) bd += rel_pos[n*8 + r] * dW1[(384 + r)*CC + j];
            val = bd;
        } else {
            float br = rb1[j - 128];
            #pragma unroll
            for (int r = 0; r < 8; ++r) br += rel_pos[n*8 + r] * rW1[(384 + r)*CC + (j-128)];
            val = br;
        }
    }
    return val;
}

// ================= setup: 41 small parallel blocks =================
// 0..15: B frag per n16 | 16..31: U frag per n16 | 32..39: Wcomb frag per n16 | 40: vbo+map
__global__ void setup_kernel(const float* __restrict__ dW1, const float* __restrict__ db1,
                             const float* __restrict__ rW1, const float* __restrict__ rb1,
                             const float* __restrict__ rel_pos,
                             const float* __restrict__ vW, const float* __restrict__ oW,
                             const float* __restrict__ vb) {
    extern __shared__ char s[];
    const int tid = threadIdx.x;
    const int warp = tid >> 5, lane = tid & 31;
    const uint32_t sb = smem_u32(s);
    const int bid = blockIdx.x;

    if (bid < 16) {
        // --- edge B fragments for n16 block bid: rows jg = bid*16 + jl ---
        for (int idx = tid; idx < 16*KP; idx += NT) {
            int jl = idx / KP, c = idx - (idx / KP)*KP;
            *(__nv_bfloat16*)(s + jl*ROWB + c*2) =
                __float2bfloat16(b_val(bid*16 + jl, c, dW1, db1, rW1, rb1, rel_pos));
        }
        __syncthreads();
        if (warp == 0) {
            uint32_t baddr = sb + (uint32_t)(((lane & 7) + ((lane >> 4) << 3))*ROWB
                           + (((lane >> 3) & 1) << 4));
            #pragma unroll
            for (int k = 0; k < 9; ++k) {
                uint32_t bf[4];
                ldm_x4(bf, baddr + k*32);
                g_Bfrag[(bid*9 + k)*32 + lane] = make_uint4(bf[0], bf[1], bf[2], bf[3]);
            }
        }
    } else if (bid < 32) {
        // --- U fragments for n16 block ni = bid-16 ---
        int ni = bid - 16;
        for (int idx = tid; idx < 16*128; idx += NT) {
            int jl = idx >> 7, c = idx & 127;
            int jg = ni*16 + jl;
            float val = (jg < 128)
                ? dW1[c*CC + jg]         + dW1[(256 + c)*CC + jg]
                : rW1[c*CC + (jg - 128)] + rW1[(256 + c)*CC + (jg - 128)];
            *(__nv_bfloat16*)(s + jl*CROWB + c*2) = __float2bfloat16(val);
        }
        __syncthreads();
        if (warp == 0) {
            uint32_t baddr = sb + (uint32_t)(((lane & 7) + ((lane >> 4) << 3))*CROWB
                           + (((lane >> 3) & 1) << 4));
            #pragma unroll
            for (int k = 0; k < 8; ++k) {
                uint32_t bf[4];
                ldm_x4(bf, baddr + k*32);
                g_Ufrag[(ni*8 + k)*32 + lane] = make_uint4(bf[0], bf[1], bf[2], bf[3]);
            }
        }
    } else if (bid < 40) {
        // --- Wcomb fragments for n16 block ni = bid-32 (outputs d in [ni*16, ni*16+16)) ---
        int ni = bid - 32;
        float* ows = (float*)s;                        // [128 e][16 jl]
        char* stg = s + 8192;
        for (int idx = tid; idx < 128*16; idx += NT) {
            int e = idx >> 4, jl = idx & 15;
            ows[e*16 + jl] = oW[e*CC + ni*16 + jl];
        }
        __syncthreads();
        for (int idx = tid; idx < 16*128; idx += NT) {
            int jl = idx >> 7, c = idx & 127;          // element (c, jl)
            float su = 0.0f;
            #pragma unroll 4
            for (int e = 0; e < 128; ++e)
                su = fmaf(vW[c*CC + e], ows[e*16 + jl], su);
            *(__nv_bfloat16*)(stg + jl*CROWB + c*2) = __float2bfloat16(su);
        }
        __syncthreads();
        if (warp == 0) {
            uint32_t baddr = sb + 8192u + (uint32_t)(((lane & 7) + ((lane >> 4) << 3))*CROWB
                           + (((lane >> 3) & 1) << 4));
            #pragma unroll
            for (int k = 0; k < 8; ++k) {
                uint32_t bf[4];
                ldm_x4(bf, baddr + k*32);
                g_Wfrag[(ni*8 + k)*32 + lane] = make_uint4(bf[0], bf[1], bf[2], bf[3]);
            }
        }
    } else {
        // --- vbo + gather map ---
        if (tid < 128) {
            float su = 0.0f;
            #pragma unroll 4
            for (int e = 0; e < 128; ++e) su = fmaf(vb[e], oW[e*CC + tid], su);
            g_vbo[tid] = su;
        }
        for (int r0 = tid; r0 < 1152; r0 += NT) {
            int sft = r0 >> 7;
            int c2  = r0 & 127;
            int f   = c2*9 + sft;
            int n   = f >> 7;
            int c   = f & 127;
            int di  = sft / 3;
            int dj  = sft - di*3;
            uint32_t dst = (uint32_t)(n*ROWB + c*2);
            g_map[r0] = (dst << 11) | ((uint32_t)di << 9) | ((uint32_t)dj << 7) | (uint32_t)c2;
        }
    }
}

// ================= main fused kernel: CTA = 16 positions =================
__global__ __launch_bounds__(NT, 2)
void eml_main_kernel(const float* __restrict__ tokens,
                     const float* __restrict__ ln1_g, const float* __restrict__ ln1_b,
                     const float* __restrict__ ln2_g, const float* __restrict__ ln2_b,
                     const float* __restrict__ dW2, const float* __restrict__ db2,
                     const float* __restrict__ rW2, const float* __restrict__ rb2,
                     const float* __restrict__ ob,
                     const float* __restrict__ p_gamma, const float* __restrict__ p_lam,
                     const float* __restrict__ p_bias,
                     float* __restrict__ out) {
    extern __shared__ char smem[];
    float* smf = (float*)smem;
    float* cuS = (float*)(smem + CU_OFFB);        // [16][256]
    float* uS  = (float*)(smem + A_OFFB);         // aliases edge A (dead by then)
    const uint32_t smb = smem_u32(smem);

    const int tid  = threadIdx.x;
    const int warp = tid >> 5, lane = tid & 31;
    const int blk = blockIdx.x;
    const int b   = blk >> 10;
    const int t   = blk & 1023;
    const int h   = t >> 3;
    const int w0  = (t & 7) << 4;
    const int rowbase = (b*HH + h)*WW + w0;

    // ---- phase 0a: LN1 halo (54 spatial rows -> bf16) ----
    for (int q = warp; q < 54; q += 16) {
        int di = q / 18, wi = q - di*18;
        int hh = h + di - 1, ww = w0 + wi - 1;
        char* dstrow = smem + HALO_OFFB + q*CROWB;
        if (((unsigned)hh < HH) && ((unsigned)ww < WW)) {
            float4 x = reinterpret_cast<const float4*>(
                tokens + (long)((b*HH + hh)*WW + ww)*CC)[lane];
            float su = x.x + x.y + x.z + x.w;
            #pragma unroll
            for (int o = 16; o; o >>= 1) su += __shfl_xor_sync(0xffffffffu, su, o);
            float m = su * (1.0f/128.0f);
            float dx = x.x - m, dy = x.y - m, dz = x.z - m, dw = x.w - m;
            float v = dx*dx + dy*dy + dz*dz + dw*dw;
            #pragma unroll
            for (int o = 16; o; o >>= 1) v += __shfl_xor_sync(0xffffffffu, v, o);
            float rs = rsqrtf(v * (1.0f/128.0f) + 1e-5f);
            int c = lane * 4;
            float o0 = dx*rs*ln1_g[c+0] + ln1_b[c+0];
            float o1 = dy*rs*ln1_g[c+1] + ln1_b[c+1];
            float o2 = dz*rs*ln1_g[c+2] + ln1_b[c+2];
            float o3 = dw*rs*ln1_g[c+3] + ln1_b[c+3];
            __nv_bfloat162 lo = __floats2bfloat162_rn(o0, o1);
            __nv_bfloat162 hi = __floats2bfloat162_rn(o2, o3);
            uint2 st;
            st.x = *reinterpret_cast<uint32_t*>(&lo);
            st.y = *reinterpret_cast<uint32_t*>(&hi);
            *(uint2*)(dstrow + lane*8) = st;
        } else {
            *(uint2*)(dstrow + lane*8) = make_uint2(0u, 0u);   // pad-after-LN = zeros
        }
    }
    // ---- phase 0b: ext-col zero + one-hot; w2/vbo/ob stage ----
    if (tid < NEDGE) {
        char* row = smem + A_OFFB + tid*ROWB;
        uint4 z = make_uint4(0, 0, 0, 0);
        *(uint4*)(row + 256) = z;
        *(uint4*)(row + 272) = z;
        *(uint4*)(row + 288) = z;
        int n = tid - (tid / 9)*9;
        *(__nv_bfloat16*)(row + (128 + n)*2) = __float2bfloat16(1.0f);
    }
    if (tid < 256)      smf[F_W2 + tid] = (tid < 128) ? dW2[tid] : rW2[tid - 128];
    else if (tid < 384) smf[F_VBO + tid - 256] = g_vbo[tid - 256];
    else if (tid < 512 && tid >= 384) smf[F_OB + tid - 384] = ob[tid - 384];
    __syncthreads();

    // ---- phase 1: gather (smem halo -> edge A), no bounds checks ----
    for (int r0 = tid; r0 < 1152; r0 += NT) {
        uint32_t pk = g_map[r0];
        int c2 = pk & 127;
        int dj = (pk >> 7) & 3;
        int di = (pk >> 9) & 3;
        uint32_t dst = pk >> 11;
        const char* srcbase = smem + HALO_OFFB + (di*18 + dj)*CROWB + c2*2;
        char* dbase = smem + A_OFFB + dst;
        #pragma unroll
        for (int p = 0; p < 16; ++p) {
            *(uint16_t*)(dbase + p*(9*ROWB)) = *(const uint16_t*)(srcbase + p*CROWB);
        }
    }
    __syncthreads();

    // ---- phase 2: cu GEMM (cen = halo rows 19..34 @ U) ----
    {
        uint32_t aaddr = smb + WS_OFFB + (lane & 15)*CROWB + ((lane >> 4) << 4);
        uint32_t af[8][4];
        #pragma unroll
        for (int k = 0; k < 8; ++k) ldm_x4(af[k], aaddr + k*32);
        float cA[4] = {0,0,0,0}, cB[4] = {0,0,0,0};
        const uint4* up = g_Ufrag + (warp*8)*32 + lane;
        #pragma unroll
        for (int k = 0; k < 8; ++k) {
            uint4 bf = up[k*32];
            mma16816(cA, af[k], bf.x, bf.y);
            mma16816(cB, af[k], bf.z, bf.w);
        }
        int r = lane >> 2, jc = warp*16 + (lane & 3)*2;
        cuS[r*256 + jc]           = cA[0];
        cuS[r*256 + jc + 1]       = cA[1];
        cuS[(r + 8)*256 + jc]     = cA[2];
        cuS[(r + 8)*256 + jc + 1] = cA[3];
        cuS[r*256 + jc + 8]       = cB[0];
        cuS[r*256 + jc + 9]       = cB[1];
        cuS[(r + 8)*256 + jc + 8] = cB[2];
        cuS[(r + 8)*256 + jc + 9] = cB[3];
    }
    __syncthreads();

    // ---- phase 3: edge GEMM, warp = n16 block (9 m-tiles each) ----
    {
        const uint32_t Abase = smb + A_OFFB;
        const int ni = warp;
        const uint4* bp = g_Bfrag + (ni*9)*32 + lane;
        const int jgg = ni*16 + (lane & 3)*2;
        const float w20 = smf[F_W2 + jgg],     w21 = smf[F_W2 + jgg + 1];
        const float w28 = smf[F_W2 + jgg + 8], w29 = smf[F_W2 + jgg + 9];
        #pragma unroll
        for (int mt = 0; mt < 9; ++mt) {
            int m0 = mt * 16;
            int r0 = m0 + (lane >> 2);
            int p0 = r0 / 9, p1 = (r0 + 8) / 9;
            uint32_t aaddr = Abase + (m0 + (lane & 15))*ROWB + ((lane >> 4) << 4);
            float acc[8];
            #pragma unroll
            for (int q = 0; q < 8; ++q) acc[q] = 0.0f;
            #pragma unroll
            for (int k = 0; k < 9; ++k) {
                uint32_t af[4];
                ldm_x4(af, aaddr + k*32);
                uint4 bf = bp[k*32];
                mma16816(acc,     af, bf.x, bf.y);
                mma16816(acc + 4, af, bf.z, bf.w);
            }
            const float* cu0 = cuS + p0*256 + jgg;
            const float* cu1 = cuS + p1*256 + jgg;
            float part0 = gelu_exact(acc[0] + cu0[0])*w20 + gelu_exact(acc[1] + cu0[1])*w21
                        + gelu_exact(acc[4] + cu0[8])*w28 + gelu_exact(acc[5] + cu0[9])*w29;
            float part1 = gelu_exact(acc[2] + cu1[0])*w20 + gelu_exact(acc[3] + cu1[1])*w21
                        + gelu_exact(acc[6] + cu1[8])*w28 + gelu_exact(acc[7] + cu1[9])*w29;
            part0 += __shfl_xor_sync(0xffffffffu, part0, 1);
            part0 += __shfl_xor_sync(0xffffffffu, part0, 2);
            part1 += __shfl_xor_sync(0xffffffffu, part1, 1);
            part1 += __shfl_xor_sync(0xffffffffu, part1, 2);
            if ((lane & 3) == 0) {
                smf[F_PART + r0*16 + ni]       = part0;
                smf[F_PART + (r0 + 8)*16 + ni] = part1;
            }
        }
    }
    __syncthreads();

    // ---- phase 4: EML gate ----
    const float gamma = *p_gamma, lam = *p_lam, ebias = *p_bias;
    if (tid < NEDGE) {
        const float4* pr = (const float4*)(smf + F_PART + tid*16);
        float4 a = pr[0], b4 = pr[1], c4 = pr[2], e4 = pr[3];
        float d = a.x + a.y + a.z + a.w + b4.x + b4.y + b4.z + b4.w + db2[0];
        float r = c4.x + c4.y + c4.z + c4.w + e4.x + e4.y + e4.z + e4.w + rb2[0];
        float sp = fmaxf(r, 0.0f) + log1pf(expf(-fabsf(r)));
        float en = gamma * d / (lam * sp + 1e-6f) + ebias;
        en = fminf(fmaxf(en, -3.0f), 3.0f);
        smf[F_GATE + tid] = 1.0f / (1.0f + expf(-en));
    }
    __syncthreads();
    if (tid < TILE_P) {
        float s = 0.0f;
        #pragma unroll
        for (int n = 0; n < 9; ++n) s += smf[F_GATE + tid*9 + n];
        smf[F_SG + tid]   = s;
        smf[F_INVM + tid] = 1.0f / fmaxf(s, 1e-6f);
    }
    __syncthreads();

    // ---- phase 5: ws = (sum_n gate*nbhd)/mass -> bf16 tile (halo center rows, halo dead) ----
    {
        int p = tid >> 5;
        int c0 = lane * 4;
        float im = smf[F_INVM + p];
        float gr[9];
        #pragma unroll
        for (int n = 0; n < 9; ++n) gr[n] = smf[F_GATE + p*9 + n];
        float s0 = 0, s1 = 0, s2 = 0, s3 = 0;
        #pragma unroll
        for (int n = 0; n < 9; ++n) {
            const char* row = smem + A_OFFB + (p*9 + n)*ROWB;
            uint2 u = *(const uint2*)(row + c0*2);
            __nv_bfloat162 lo = *reinterpret_cast<__nv_bfloat162*>(&u.x);
            __nv_bfloat162 hi = *reinterpret_cast<__nv_bfloat162*>(&u.y);
            s0 += gr[n] * __bfloat162float(lo.x);
            s1 += gr[n] * __bfloat162float(lo.y);
            s2 += gr[n] * __bfloat162float(hi.x);
            s3 += gr[n] * __bfloat162float(hi.y);
        }
        __nv_bfloat162 lo2 = __floats2bfloat162_rn(s0*im, s1*im);
        __nv_bfloat162 hi2 = __floats2bfloat162_rn(s2*im, s3*im);
        uint2 st;
        st.x = *reinterpret_cast<uint32_t*>(&lo2);
        st.y = *reinterpret_cast<uint32_t*>(&hi2);
        *(uint2*)(smem + WS_OFFB + p*CROWB + c0*2) = st;
    }
    __syncthreads();

    // ---- phase 6: u GEMM (ws @ Wcomb) + tokens + coef*vbo + ob -> uS f32 ----
    if (warp < 8) {
        uint32_t aaddr = smb + WS_OFFB + (lane & 15)*CROWB + ((lane >> 4) << 4);
        uint32_t af[8][4];
        #pragma unroll
        for (int k = 0; k < 8; ++k) ldm_x4(af[k], aaddr + k*32);
        float cA[4] = {0,0,0,0}, cB[4] = {0,0,0,0};
        const uint4* wp = g_Wfrag + (warp*8)*32 + lane;
        #pragma unroll
        for (int k = 0; k < 8; ++k) {
            uint4 bf = wp[k*32];
            mma16816(cA, af[k], bf.x, bf.y);
            mma16816(cB, af[k], bf.z, bf.w);
        }
        int r = lane >> 2, jc = (lane & 3)*2, j0 = warp*16;
        int p0 = r, p1 = r + 8;
        float coef0 = smf[F_SG + p0] * smf[F_INVM + p0];
        float coef1 = smf[F_SG + p1] * smf[F_INVM + p1];
        int d00 = j0 + jc, d10 = j0 + 8 + jc;
        float2 tA0 = *(const float2*)(tokens + (long)(rowbase + p0)*CC + d00);
        float2 tA1 = *(const float2*)(tokens + (long)(rowbase + p0)*CC + d10);
        float2 tB0 = *(const float2*)(tokens + (long)(rowbase + p1)*CC + d00);
        float2 tB1 = *(const float2*)(tokens + (long)(rowbase + p1)*CC + d10);
        uS[p0*CC + d00]     = cA[0] + tA0.x + coef0*smf[F_VBO + d00]     + smf[F_OB + d00];
        uS[p0*CC + d00 + 1] = cA[1] + tA0.y + coef0*smf[F_VBO + d00 + 1] + smf[F_OB + d00 + 1];
        uS[p1*CC + d00]     = cA[2] + tB0.x + coef1*smf[F_VBO + d00]     + smf[F_OB + d00];
        uS[p1*CC + d00 + 1] = cA[3] + tB0.y + coef1*smf[F_VBO + d00 + 1] + smf[F_OB + d00 + 1];
        uS[p0*CC + d10]     = cB[0] + tA1.x + coef0*smf[F_VBO + d10]     + smf[F_OB + d10];
        uS[p0*CC + d10 + 1] = cB[1] + tA1.y + coef0*smf[F_VBO + d10 + 1] + smf[F_OB + d10 + 1];
        uS[p1*CC + d10]     = cB[2] + tB1.x + coef1*smf[F_VBO + d10]     + smf[F_OB + d10];
        uS[p1*CC + d10 + 1] = cB[3] + tB1.y + coef1*smf[F_VBO + d10 + 1] + smf[F_OB + d10 + 1];
    }
    __syncthreads();

    // ---- phase 7: LN2 + store (warp per position) ----
    {
        int p = warp;
        float4 x = reinterpret_cast<const float4*>(uS + p*CC)[lane];
        float s = x.x + x.y + x.z + x.w;
        #pragma unroll
        for (int o = 16; o; o >>= 1) s += __shfl_xor_sync(0xffffffffu, s, o);
        float m = s * (1.0f/128.0f);
        float dx = x.x - m, dy = x.y - m, dz = x.z - m, dw = x.w - m;
        float v = dx*dx + dy*dy + dz*dz + dw*dw;
        #pragma unroll
        for (int o = 16; o; o >>= 1) v += __shfl_xor_sync(0xffffffffu, v, o);
        float rs = rsqrtf(v * (1.0f/128.0f) + 1e-5f);
        int c = lane * 4;
        float4 o4;
        o4.x = dx*rs*ln2_g[c+0] + ln2_b[c+0];
        o4.y = dy*rs*ln2_g[c+1] + ln2_b[c+1];
        o4.z = dz*rs*ln2_g[c+2] + ln2_b[c+2];
        o4.w = dw*rs*ln2_g[c+3] + ln2_b[c+3];
        reinterpret_cast<float4*>(out + (long)(rowbase + p)*CC)[lane] = o4;
    }
}

// ---------------- launch ----------------
extern "C" void kernel_launch(void* const* d_in, const int* in_sizes, int n_in,
                              void* d_out, int out_size) {
    const float* tokens = (const float*)d_in[0];
    const float* ln1_g  = (const float*)d_in[1];
    const float* ln1_b  = (const float*)d_in[2];
    const float* ln2_g  = (const float*)d_in[3];
    const float* ln2_b  = (const float*)d_in[4];
    const float* rel_pos= (const float*)d_in[5];
    const float* dW1    = (const float*)d_in[6];
    const float* db1    = (const float*)d_in[7];
    const float* dW2    = (const float*)d_in[8];
    const float* db2    = (const float*)d_in[9];
    const float* rW1    = (const float*)d_in[10];
    const float* rb1    = (const float*)d_in[11];
    const float* rW2    = (const float*)d_in[12];
    const float* rb2    = (const float*)d_in[13];
    const float* vW     = (const float*)d_in[14];
    const float* vb     = (const float*)d_in[15];
    const float* oW     = (const float*)d_in[16];
    const float* ob     = (const float*)d_in[17];
    const float* gamma  = (const float*)d_in[18];
    const float* lam    = (const float*)d_in[19];
    const float* ebias  = (const float*)d_in[20];
    float* out = (float*)d_out;

    cudaFuncSetAttribute(setup_kernel, cudaFuncAttributeMaxDynamicSharedMemorySize, SETUP_SMEM);
    setup_kernel<<<41, NT, SETUP_SMEM>>>(dW1, db1, rW1, rb1, rel_pos, vW, oW, vb);
    cudaFuncSetAttribute(eml_main_kernel, cudaFuncAttributeMaxDynamicSharedMemorySize, SMEM_TOTAL);
    eml_main_kernel<<<(BB*HH*WW)/TILE_P, NT, SMEM_TOTAL>>>(tokens, ln1_g, ln1_b, ln2_g, ln2_b,
                                                           dW2, db2, rW2, rb2, ob,
                                                           gamma, lam, ebias, out);
}